// round 3
// baseline (speedup 1.0000x reference)
#include <cuda_runtime.h>
#include <math.h>

#define RT 4
#define N_AMB 1023
#define NN 1024
#define SLOPE 0.2f
#define NPB 8
#define NBLK (NN / NPB)   // 128
#define KD_RPB 8
#define KD_BLOCKS 128

// ---- scratch (__device__ globals; no allocation allowed) ----
__device__ float d_hidden1[64];
__device__ float d_gr0[256];
__device__ float d_WlT[64 * 256];
__device__ float d_WrT[64 * 256];
__device__ float d_Wd0T[64 * 64];     // transposed first-half of Wd0
__device__ float d_Wd1T[64 * 128];
__device__ float d_pm[NBLK * 4];
__device__ float d_pz[NBLK * 4];
__device__ float d_pacc[NBLK * 256];
__device__ float d_c0[64];
__device__ int   d_cnt;

__device__ __forceinline__ float leaky(float x) { return x >= 0.f ? x : SLOPE * x; }

__device__ __forceinline__ float red4(float v) {
    v += __shfl_xor_sync(0xffffffffu, v, 1, 4);
    v += __shfl_xor_sync(0xffffffffu, v, 2, 4);
    return v;
}

// smem-tiled transpose: in is O x K (row stride = istride), out is K x O.
// 256 threads; both global sides coalesced; 33-float padded tiles.
__device__ void transpose_tiled(const float* __restrict__ in, float* __restrict__ out,
                                int O, int K, int istride) {
    __shared__ float s[32][33];
    int tid = threadIdx.x;
    int c = tid & 31, rb = tid >> 5;   // col-in-tile, row-base (8 rows per step)
    for (int to = 0; to < O; to += 32) {
        for (int tk = 0; tk < K; tk += 32) {
            #pragma unroll
            for (int i = 0; i < 4; i++) {
                int oo = rb + i * 8;
                s[oo][c] = in[(to + oo) * istride + tk + c];
            }
            __syncthreads();
            #pragma unroll
            for (int i = 0; i < 4; i++) {
                int kk = rb + i * 8;
                out[(tk + kk) * O + to + c] = s[c][kk];
            }
            __syncthreads();
        }
    }
}

// ---------------------------------------------------------------------------
// KA: 5 independent blocks.
//  b0: transpose W_l (+ reset last-block counter)   b1: transpose W_r
//  b2: routing chain -> hidden_1, g_r0              b3: Wd0 (amb half)  b4: Wd1
// ---------------------------------------------------------------------------
__global__ void kA(const float* __restrict__ hidden, const float* __restrict__ ta,
                   const float* __restrict__ Wself, const float* __restrict__ bself,
                   const float* __restrict__ Wmerge, const float* __restrict__ bmerge,
                   const float* __restrict__ Wtrans, const float* __restrict__ btrans,
                   const float* __restrict__ Wl, const float* __restrict__ Wr,
                   const float* __restrict__ Wd0, const float* __restrict__ Wd1) {
    int tid = threadIdx.x;
    int b = blockIdx.x;
    if (b == 0) { if (tid == 0) d_cnt = 0; transpose_tiled(Wl, d_WlT, 256, 64, 64); return; }
    if (b == 1) { transpose_tiled(Wr, d_WrT, 256, 64, 64); return; }
    if (b == 3) { transpose_tiled(Wd0, d_Wd0T, 64, 64, 128); return; }
    if (b == 4) { transpose_tiled(Wd1, d_Wd1T, 128, 64, 64); return; }
    // ---- routing (block 2) ----
    __shared__ float s_cat[128];   // [h1 | tmp]
    __shared__ float s_in[64];
    __shared__ float s_m[64];
    int o = tid >> 2, q = tid & 3;
    if (tid < 64) s_in[tid] = hidden[tid];
    __syncthreads();
    {   // hidden_1 = hidden @ W_self^T + b_self
        float s = 0.f;
        const float4* w4 = (const float4*)(Wself + o * 64 + q * 16);
        #pragma unroll
        for (int i = 0; i < 4; i++) {
            float4 w = w4[i];
            int k = q * 16 + i * 4;
            s += w.x * s_in[k] + w.y * s_in[k + 1] + w.z * s_in[k + 2] + w.w * s_in[k + 3];
        }
        s = red4(s);
        if (q == 0) s_cat[o] = bself[o] + s;
    }
    __syncthreads();
    for (int rt = 0; rt < RT; rt++) {
        if (tid < 64)
            s_in[tid] = (ta[(rt * 3 + 0) * 64 + tid] + ta[(rt * 3 + 1) * 64 + tid] +
                         ta[(rt * 3 + 2) * 64 + tid]) * (1.f / 3.f);
        __syncthreads();
        {
            float s = 0.f;
            const float4* w4 = (const float4*)(Wtrans + rt * 4096 + o * 64 + q * 16);
            #pragma unroll
            for (int i = 0; i < 4; i++) {
                float4 w = w4[i];
                int k = q * 16 + i * 4;
                s += w.x * s_in[k] + w.y * s_in[k + 1] + w.z * s_in[k + 2] + w.w * s_in[k + 3];
            }
            s = red4(s);
            if (q == 0) s_cat[64 + o] = btrans[rt * 64 + o] + s;
        }
        __syncthreads();
        {
            float s = 0.f;
            const float4* w4 = (const float4*)(Wmerge + o * 128 + q * 32);
            #pragma unroll
            for (int i = 0; i < 8; i++) {
                float4 w = w4[i];
                int k = q * 32 + i * 4;
                s += w.x * s_cat[k] + w.y * s_cat[k + 1] + w.z * s_cat[k + 2] + w.w * s_cat[k + 3];
            }
            s = red4(s);
            if (q == 0) s_m[o] = leaky(bmerge[o] + s);
        }
        __syncthreads();
        if (tid < 64) s_cat[tid] = s_m[tid];
        __syncthreads();
    }
    if (tid < 64) d_hidden1[tid] = s_cat[tid];
    {   // g_r0[o] = hidden_1 . W_r[o,:]
        float g = 0.f;
        const float4* w4 = (const float4*)(Wr + tid * 64);
        #pragma unroll
        for (int i = 0; i < 16; i++) {
            float4 w = w4[i];
            int k = i * 4;
            g += w.x * s_cat[k] + w.y * s_cat[k + 1] + w.z * s_cat[k + 2] + w.w * s_cat[k + 3];
        }
        d_gr0[tid] = g;
    }
}

// ---------------------------------------------------------------------------
// KB: per block (8 nodes): projections, attention-row logits, online-softmax
// partial. The LAST block to finish (atomic counter) performs the global
// combine -> hidden_2 -> c0 (deterministic fixed-order reduction).
// ---------------------------------------------------------------------------
__global__ void kB(const float* __restrict__ amb, const float* __restrict__ wattn,
                   const float* __restrict__ Wd0, const float* __restrict__ bd0) {
    __shared__ float s_h[NPB][64];
    __shared__ float s_wred[NPB][8];
    __shared__ float s_e[NPB][4];
    __shared__ int s_last;
    int tid = threadIdx.x;
    int base = blockIdx.x * NPB;
    #pragma unroll
    for (int p = 0; p < 2; p++) {
        int idx = tid + p * 256;
        int r = idx >> 6, k = idx & 63;
        int j = base + r;
        s_h[r][k] = (j == 0) ? d_hidden1[k] : amb[(j - 1) * 64 + k];
    }
    __syncthreads();
    float al[NPB], ar[NPB];
    #pragma unroll
    for (int r = 0; r < NPB; r++) { al[r] = 0.f; ar[r] = 0.f; }
    #pragma unroll 4
    for (int k = 0; k < 64; k++) {
        float wl = d_WlT[k * 256 + tid];
        float wr = d_WrT[k * 256 + tid];
        #pragma unroll
        for (int r = 0; r < NPB; r++) {
            float hv = s_h[r][k];
            al[r] = fmaf(hv, wl, al[r]);
            ar[r] = fmaf(hv, wr, ar[r]);
        }
    }
    float g0 = d_gr0[tid];
    float wa = wattn[tid & 63];
    int lane = tid & 31, warp = tid >> 5;
    #pragma unroll
    for (int r = 0; r < NPB; r++) {
        float c = leaky(al[r] + g0) * wa;
        #pragma unroll
        for (int off = 16; off; off >>= 1) c += __shfl_down_sync(0xffffffffu, c, off);
        if (lane == 0) s_wred[r][warp] = c;
    }
    __syncthreads();
    if (tid < NPB * 4) {
        int r = tid >> 2, h = tid & 3;
        s_e[r][h] = s_wred[r][2 * h] + s_wred[r][2 * h + 1];
    }
    __syncthreads();
    int h = tid >> 6;
    float m = -1e30f;
    #pragma unroll
    for (int r = 0; r < NPB; r++) m = fmaxf(m, s_e[r][h]);
    float z = 0.f, acc = 0.f;
    #pragma unroll
    for (int r = 0; r < NPB; r++) {
        float w = __expf(s_e[r][h] - m);
        z += w;
        acc = fmaf(w, ar[r], acc);
    }
    d_pacc[blockIdx.x * 256 + tid] = acc;
    if ((tid & 63) == 0) {
        d_pm[blockIdx.x * 4 + h] = m;
        d_pz[blockIdx.x * 4 + h] = z;
    }
    // ---- last-block-done combine ----
    __threadfence();
    __syncthreads();
    if (tid == 0) s_last = (atomicAdd(&d_cnt, 1) == gridDim.x - 1);
    __syncthreads();
    if (!s_last) return;
    __threadfence();
    {
        __shared__ float s_pm[512], s_pz[512], s_scale[512];
        __shared__ float s_M[4], s_Zinv[4];
        __shared__ float s_res[256], s_h2[64];
        for (int i = tid; i < 512; i += 256) { s_pm[i] = d_pm[i]; s_pz[i] = d_pz[i]; }
        __syncthreads();
        if (warp < 4) {
            float mm = -1e30f;
            for (int b = lane; b < NBLK; b += 32) mm = fmaxf(mm, s_pm[b * 4 + warp]);
            #pragma unroll
            for (int off = 16; off; off >>= 1) mm = fmaxf(mm, __shfl_xor_sync(0xffffffffu, mm, off));
            if (lane == 0) s_M[warp] = mm;
        }
        __syncthreads();
        for (int i = tid; i < 512; i += 256) s_scale[i] = __expf(s_pm[i] - s_M[i & 3]);
        __syncthreads();
        if (warp < 4) {
            float zz = 0.f;
            for (int b = lane; b < NBLK; b += 32) zz += s_pz[b * 4 + warp] * s_scale[b * 4 + warp];
            #pragma unroll
            for (int off = 16; off; off >>= 1) zz += __shfl_xor_sync(0xffffffffu, zz, off);
            if (lane == 0) s_Zinv[warp] = 1.f / zz;
        }
        __syncthreads();
        float a2 = 0.f;
        #pragma unroll 8
        for (int b = 0; b < NBLK; b++) a2 = fmaf(d_pacc[b * 256 + tid], s_scale[b * 4 + h], a2);
        s_res[tid] = a2 * s_Zinv[h];
        __syncthreads();
        if (tid < 64)
            s_h2[tid] = 0.25f * (s_res[tid] + s_res[64 + tid] + s_res[128 + tid] + s_res[192 + tid]);
        __syncthreads();
        #pragma unroll
        for (int i = 0; i < 8; i++) {
            int o = warp * 8 + i;
            float p = s_h2[lane] * Wd0[o * 128 + 64 + lane] +
                      s_h2[lane + 32] * Wd0[o * 128 + 96 + lane];
            #pragma unroll
            for (int off = 16; off; off >>= 1) p += __shfl_down_sync(0xffffffffu, p, off);
            if (lane == 0) d_c0[o] = bd0[o] + p;
        }
    }
}

// ---------------------------------------------------------------------------
// KD: type_define MLP, register-tiled: 128 blocks x 128 threads, 8 rows/block.
// Transposed weights -> coalesced weight loads, smem-broadcast activations,
// no shuffles in stages 1-2.
// ---------------------------------------------------------------------------
__global__ void kD(const float* __restrict__ amb,
                   const float* __restrict__ bd1,
                   const float* __restrict__ Wd2, const float* __restrict__ bd2,
                   float* __restrict__ out) {
    __shared__ float s_x[KD_RPB][64];
    __shared__ float s_y0[KD_RPB][64];
    __shared__ float s_y1[KD_RPB][130];   // padded stride vs stage-3 banks
    int tid = threadIdx.x;
    int row0 = blockIdx.x * KD_RPB;
    #pragma unroll
    for (int p = 0; p < 4; p++) {
        int idx = tid + p * 128;
        int r = idx >> 6, k = idx & 63;
        int j = row0 + r;
        s_x[r][k] = (j < N_AMB) ? amb[j * 64 + k] : 0.f;
    }
    __syncthreads();
    // stage 1: 64 outputs; 2 threads per output, 4 rows each
    {
        int o = tid & 63, rg = (tid >> 6) * 4;
        float a0 = 0.f, a1 = 0.f, a2 = 0.f, a3 = 0.f;
        #pragma unroll 4
        for (int k = 0; k < 64; k++) {
            float w = d_Wd0T[k * 64 + o];
            a0 = fmaf(s_x[rg + 0][k], w, a0);
            a1 = fmaf(s_x[rg + 1][k], w, a1);
            a2 = fmaf(s_x[rg + 2][k], w, a2);
            a3 = fmaf(s_x[rg + 3][k], w, a3);
        }
        float c = d_c0[o];
        s_y0[rg + 0][o] = leaky(c + a0);
        s_y0[rg + 1][o] = leaky(c + a1);
        s_y0[rg + 2][o] = leaky(c + a2);
        s_y0[rg + 3][o] = leaky(c + a3);
    }
    __syncthreads();
    // stage 2: 128 outputs; 1 thread per output, all 8 rows
    {
        float b[KD_RPB];
        #pragma unroll
        for (int r = 0; r < KD_RPB; r++) b[r] = 0.f;
        #pragma unroll 4
        for (int k = 0; k < 64; k++) {
            float w = d_Wd1T[k * 128 + tid];
            #pragma unroll
            for (int r = 0; r < KD_RPB; r++) b[r] = fmaf(s_y0[r][k], w, b[r]);
        }
        float bb = bd1[tid];
        #pragma unroll
        for (int r = 0; r < KD_RPB; r++) s_y1[r][tid] = leaky(bb + b[r]);
    }
    __syncthreads();
    // stage 3: 8 rows x 4 outputs, 4 threads per dot (interleaved k), + sigmoid
    {
        int r = tid >> 4, sub = tid & 15, o = sub >> 2, q = sub & 3;
        float p = 0.f;
        #pragma unroll 8
        for (int kk = 0; kk < 32; kk++) {
            int k = q + 4 * kk;
            p = fmaf(s_y1[r][k], Wd2[o * 128 + k], p);
        }
        p = red4(p);
        int j = row0 + r;
        if (q == 0 && j < N_AMB)
            out[j * 4 + o] = 1.f / (1.f + __expf(-(bd2[o] + p)));
    }
}

// ---------------------------------------------------------------------------
extern "C" void kernel_launch(void* const* d_in, const int* in_sizes, int n_in,
                              void* d_out, int out_size) {
    const float* hidden = (const float*)d_in[0];
    const float* amb    = (const float*)d_in[1];
    const float* ta     = (const float*)d_in[2];
    const float* Wself  = (const float*)d_in[3];
    const float* bself  = (const float*)d_in[4];
    const float* Wmerge = (const float*)d_in[5];
    const float* bmerge = (const float*)d_in[6];
    const float* Wtrans = (const float*)d_in[7];
    const float* btrans = (const float*)d_in[8];
    const float* Wl     = (const float*)d_in[9];
    const float* Wr     = (const float*)d_in[10];
    const float* wattn  = (const float*)d_in[11];
    const float* Wd0    = (const float*)d_in[12];
    const float* bd0    = (const float*)d_in[13];
    const float* Wd1    = (const float*)d_in[14];
    const float* bd1    = (const float*)d_in[15];
    const float* Wd2    = (const float*)d_in[16];
    const float* bd2    = (const float*)d_in[17];
    float* out = (float*)d_out;

    kA<<<5, 256>>>(hidden, ta, Wself, bself, Wmerge, bmerge, Wtrans, btrans,
                   Wl, Wr, Wd0, Wd1);
    kB<<<NBLK, 256>>>(amb, wattn, Wd0, bd0);
    kD<<<KD_BLOCKS, 128>>>(amb, bd1, Wd2, bd2, out);
}

// round 4
// speedup vs baseline: 1.4071x; 1.4071x over previous
#include <cuda_runtime.h>
#include <math.h>

#define RT 4
#define N_AMB 1023
#define SLOPE 0.2f
#define NPB 8
#define NBLK 128

// ---- scratch (__device__ globals; no allocation allowed) ----
__device__ float d_gr0[256];
__device__ float d_pm[NBLK * 4];
__device__ float d_pz[NBLK * 4];
__device__ float d_pacc[NBLK * 256];
__device__ float d_c0[64];
__device__ int   d_flag1;   // set by block 0 after routing; reset by combiner
__device__ int   d_flag2;   // set by combiner; reset by last block through cnt2
__device__ int   d_cnt1;    // combine arrival counter; reset by combiner
__device__ int   d_cnt2;    // flag2-passed counter; reset by its last arriver

__device__ __forceinline__ float leaky(float x) { return x >= 0.f ? x : SLOPE * x; }
__device__ __forceinline__ float red4(float v) {
    v += __shfl_xor_sync(0xffffffffu, v, 1);
    v += __shfl_xor_sync(0xffffffffu, v, 2);
    return v;
}
__device__ __forceinline__ float red8(float v) {
    v += __shfl_xor_sync(0xffffffffu, v, 1);
    v += __shfl_xor_sync(0xffffffffu, v, 2);
    v += __shfl_xor_sync(0xffffffffu, v, 4);
    return v;
}
__device__ __forceinline__ float warpsum(float v) {
    #pragma unroll
    for (int off = 16; off; off >>= 1) v += __shfl_xor_sync(0xffffffffu, v, off);
    return v;
}
// 16-term dot: w points at 16 consecutive weights (16B-aligned), x at 16 activations
__device__ __forceinline__ float dot16(const float* __restrict__ w, const float* __restrict__ x) {
    const float4* w4 = (const float4*)w;
    float4 w0 = w4[0], w1 = w4[1], w2 = w4[2], w3 = w4[3];
    return w0.x*x[0] + w0.y*x[1] + w0.z*x[2] + w0.w*x[3]
         + w1.x*x[4] + w1.y*x[5] + w1.z*x[6] + w1.w*x[7]
         + w2.x*x[8] + w2.y*x[9] + w2.z*x[10] + w2.w*x[11]
         + w3.x*x[12] + w3.y*x[13] + w3.z*x[14] + w3.w*x[15];
}

__global__ void __launch_bounds__(256, 1)
mega(const float* __restrict__ hidden, const float* __restrict__ amb,
     const float* __restrict__ ta,
     const float* __restrict__ Wself,  const float* __restrict__ bself,
     const float* __restrict__ Wmerge, const float* __restrict__ bmerge,
     const float* __restrict__ Wtrans, const float* __restrict__ btrans,
     const float* __restrict__ Wl,     const float* __restrict__ Wr,
     const float* __restrict__ wattn,
     const float* __restrict__ Wd0,    const float* __restrict__ bd0,
     const float* __restrict__ Wd1,    const float* __restrict__ bd1,
     const float* __restrict__ Wd2,    const float* __restrict__ bd2,
     float* __restrict__ out) {
    __shared__ float s_h[NPB][64];          // node features; reused as MLP input
    __shared__ float s_wred[NPB][8];
    __shared__ float s_e[NPB];
    __shared__ int   s_last;
    // routing scratch (block 0 only)
    __shared__ float s_inh[64], s_avg[256], s_tmp[256], s_cat[128], s_new[64];
    // combine scratch (one block only)
    __shared__ float s_pm[512], s_pz[512], s_scale[512];
    __shared__ float s_M[4], s_Zinv[4], s_res[256], s_h2[64];
    // MLP scratch
    __shared__ float s_y0[NPB][64];
    __shared__ float s_y1[NPB][128];

    const int tid = threadIdx.x, lane = tid & 31, warp = tid >> 5;
    const int q = tid & 3, oid = tid >> 2;      // 4 threads per output column
    const int blk = blockIdx.x;
    const int base = blk * NPB;

    // ---- load node features (node 0 = hidden_1, filled by routing below) ----
    #pragma unroll
    for (int p = 0; p < 2; p++) {
        int idx = tid + p * 256, r = idx >> 6, k = idx & 63, j = base + r;
        if (j > 0) s_h[r][k] = amb[(j - 1) * 64 + k];
    }

    // ================= block 0: routing chain =================
    if (blk == 0) {
        if (tid < 64) s_inh[tid] = hidden[tid];
        {   // mean over agents, all RT in parallel: s_avg[rt*64 + k]
            int rt = tid >> 6, oo = tid & 63;
            s_avg[tid] = (ta[(rt * 3 + 0) * 64 + oo] + ta[(rt * 3 + 1) * 64 + oo] +
                          ta[(rt * 3 + 2) * 64 + oo]) * (1.f / 3.f);
        }
        __syncthreads();
        {   // hidden_1_0 = hidden @ Wself^T + bself  (4 thr/output)
            float s = red4(dot16(Wself + oid * 64 + q * 16, &s_inh[q * 16]));
            if (q == 0) s_cat[oid] = bself[oid] + s;
        }
        {   // tmp[rt] all in parallel (1 thr/output) — independent of the chain
            int rt = tid >> 6, oo = tid & 63;
            const float* av = &s_avg[rt * 64];
            float t = btrans[rt * 64 + oo];
            t += dot16(Wtrans + rt * 4096 + oo * 64,      av);
            t += dot16(Wtrans + rt * 4096 + oo * 64 + 16, av + 16);
            t += dot16(Wtrans + rt * 4096 + oo * 64 + 32, av + 32);
            t += dot16(Wtrans + rt * 4096 + oo * 64 + 48, av + 48);
            s_tmp[tid] = t;
        }
        __syncthreads();
        for (int rt = 0; rt < RT; rt++) {   // only the merge chain is serial
            if (tid < 64) s_cat[64 + tid] = s_tmp[rt * 64 + tid];
            __syncthreads();
            float m = dot16(Wmerge + oid * 128 + q * 32,      &s_cat[q * 32])
                    + dot16(Wmerge + oid * 128 + q * 32 + 16, &s_cat[q * 32 + 16]);
            m = red4(m);
            if (q == 0) s_new[oid] = leaky(bmerge[oid] + m);
            __syncthreads();
            if (tid < 64) s_cat[tid] = s_new[tid];
            __syncthreads();
        }
        if (tid < 64) s_h[0][tid] = s_cat[tid];
        #pragma unroll
        for (int c = 0; c < 4; c++) {       // g_r0 = hidden_1 @ Wr^T  (coalesced)
            int o = c * 64 + oid;
            float g = red4(dot16(Wr + o * 64 + q * 16, &s_cat[q * 16]));
            if (q == 0) d_gr0[o] = g;
        }
        __threadfence();
        __syncthreads();
        if (tid == 0) *(volatile int*)&d_flag1 = 1;
    }
    __syncthreads();

    // ================= pass A: projections (no routing dependency for j>0) ==
    float al[4][8], ar[4][8];
    #pragma unroll
    for (int c = 0; c < 4; c++) {
        int o = c * 64 + oid;
        const float4* wl4 = (const float4*)(Wl + o * 64 + q * 16);
        const float4* wr4 = (const float4*)(Wr + o * 64 + q * 16);
        float4 l0 = wl4[0], l1 = wl4[1], l2 = wl4[2], l3 = wl4[3];
        float4 r0 = wr4[0], r1 = wr4[1], r2 = wr4[2], r3 = wr4[3];
        const int kb = q * 16;
        #pragma unroll
        for (int r = 0; r < NPB; r++) {
            const float* h = &s_h[r][kb];
            float xl = l0.x*h[0] + l0.y*h[1] + l0.z*h[2] + l0.w*h[3]
                     + l1.x*h[4] + l1.y*h[5] + l1.z*h[6] + l1.w*h[7]
                     + l2.x*h[8] + l2.y*h[9] + l2.z*h[10] + l2.w*h[11]
                     + l3.x*h[12] + l3.y*h[13] + l3.z*h[14] + l3.w*h[15];
            float xr = r0.x*h[0] + r0.y*h[1] + r0.z*h[2] + r0.w*h[3]
                     + r1.x*h[4] + r1.y*h[5] + r1.z*h[6] + r1.w*h[7]
                     + r2.x*h[8] + r2.y*h[9] + r2.z*h[10] + r2.w*h[11]
                     + r3.x*h[12] + r3.y*h[13] + r3.z*h[14] + r3.w*h[15];
            al[c][r] = red4(xl);
            ar[c][r] = red4(xr);
        }
    }

    // ---- wait for g_r0 (released by block 0) ----
    if (blk != 0) {
        if (tid == 0) {
            volatile int* f = &d_flag1;
            while (*f == 0) __nanosleep(64);
            __threadfence();
        }
        __syncthreads();
    }

    // ================= pass B: logits e, online-softmax partial ==============
    float wa = wattn[oid];
    #pragma unroll
    for (int c = 0; c < 4; c++) {            // chunk c == head c
        int o = c * 64 + oid;
        float g0 = d_gr0[o];
        #pragma unroll
        for (int r = 0; r < NPB; r++) {
            float cv = (q == 0) ? leaky(al[c][r] + g0) * wa : 0.f;
            cv = warpsum(cv);
            if (lane == 0) s_wred[r][warp] = cv;
        }
        __syncthreads();
        if (tid < NPB) {
            float e = 0.f;
            #pragma unroll
            for (int w = 0; w < 8; w++) e += s_wred[tid][w];
            s_e[tid] = e;
        }
        __syncthreads();
        float m = -1e30f;
        #pragma unroll
        for (int r = 0; r < NPB; r++) m = fmaxf(m, s_e[r]);
        float z = 0.f, wv[NPB];
        #pragma unroll
        for (int r = 0; r < NPB; r++) { wv[r] = __expf(s_e[r] - m); z += wv[r]; }
        if (q == 0) {
            float acc = 0.f;
            #pragma unroll
            for (int r = 0; r < NPB; r++) acc = fmaf(wv[r], ar[c][r], acc);
            d_pacc[blk * 256 + o] = acc;
        }
        if (tid == 0) { d_pm[blk * 4 + c] = m; d_pz[blk * 4 + c] = z; }
        __syncthreads();
    }

    // ---- arrive at combine ----
    __threadfence();
    __syncthreads();
    if (tid == 0) s_last = (atomicAdd(&d_cnt1, 1) == NBLK - 1);
    __syncthreads();

    // prefetch MLP input rows (overlaps combine / flag wait); s_h reused
    int row0 = blk * NPB;
    #pragma unroll
    for (int p = 0; p < 2; p++) {
        int idx = tid + p * 256, r = idx >> 6, k = idx & 63, j = row0 + r;
        s_h[r][k] = (j < N_AMB) ? amb[j * 64 + k] : 0.f;
    }

    // ================= last block: global softmax combine -> c0 ==============
    if (s_last) {
        __threadfence();    // see all blocks' partials
        for (int i = tid; i < 512; i += 256) { s_pm[i] = d_pm[i]; s_pz[i] = d_pz[i]; }
        __syncthreads();
        if (warp < 4) {
            float mm = -1e30f;
            for (int b = lane; b < NBLK; b += 32) mm = fmaxf(mm, s_pm[b * 4 + warp]);
            #pragma unroll
            for (int off = 16; off; off >>= 1) mm = fmaxf(mm, __shfl_xor_sync(0xffffffffu, mm, off));
            if (lane == 0) s_M[warp] = mm;
        }
        __syncthreads();
        for (int i = tid; i < 512; i += 256) s_scale[i] = __expf(s_pm[i] - s_M[i & 3]);
        __syncthreads();
        if (warp < 4) {
            float zz = 0.f;
            for (int b = lane; b < NBLK; b += 32) zz += s_pz[b * 4 + warp] * s_scale[b * 4 + warp];
            #pragma unroll
            for (int off = 16; off; off >>= 1) zz += __shfl_xor_sync(0xffffffffu, zz, off);
            if (lane == 0) s_Zinv[warp] = 1.f / zz;
        }
        __syncthreads();
        int hh = tid >> 6;
        float a2 = 0.f;
        #pragma unroll 16
        for (int b = 0; b < NBLK; b++) a2 = fmaf(d_pacc[b * 256 + tid], s_scale[b * 4 + hh], a2);
        s_res[tid] = a2 * s_Zinv[hh];
        __syncthreads();
        if (tid < 64)
            s_h2[tid] = 0.25f * (s_res[tid] + s_res[64 + tid] + s_res[128 + tid] + s_res[192 + tid]);
        __syncthreads();
        #pragma unroll
        for (int i = 0; i < 8; i++) {        // c0[o] = bd0[o] + h2 . Wd0[o, 64:128]
            int o = warp * 8 + i;
            float p = s_h2[lane] * Wd0[o * 128 + 64 + lane] +
                      s_h2[lane + 32] * Wd0[o * 128 + 96 + lane];
            p = warpsum(p);
            if (lane == 0) d_c0[o] = bd0[o] + p;
        }
        __threadfence();
        __syncthreads();
        if (tid == 0) {
            d_cnt1 = 0;                       // safe: every block passed flag1+cnt1
            d_flag1 = 0;
            __threadfence();
            *(volatile int*)&d_flag2 = 1;
        }
    } else {
        if (tid == 0) {
            volatile int* f = &d_flag2;
            while (*f == 0) __nanosleep(64);
            __threadfence();
        }
    }
    __syncthreads();

    // ================= MLP over this block's 8 rows ==========================
    // stage 1: 64 outputs (const half folded in c0)
    {
        float c0v = d_c0[oid];
        const float4* w4 = (const float4*)(Wd0 + oid * 128 + q * 16);
        float4 w0 = w4[0], w1 = w4[1], w2 = w4[2], w3 = w4[3];
        const int kb = q * 16;
        #pragma unroll
        for (int r = 0; r < NPB; r++) {
            const float* x = &s_h[r][kb];
            float s = w0.x*x[0] + w0.y*x[1] + w0.z*x[2] + w0.w*x[3]
                    + w1.x*x[4] + w1.y*x[5] + w1.z*x[6] + w1.w*x[7]
                    + w2.x*x[8] + w2.y*x[9] + w2.z*x[10] + w2.w*x[11]
                    + w3.x*x[12] + w3.y*x[13] + w3.z*x[14] + w3.w*x[15];
            s = red4(s);
            if (q == 0) s_y0[r][oid] = leaky(c0v + s);
        }
    }
    __syncthreads();
    // stage 2: 128 outputs
    #pragma unroll
    for (int c2 = 0; c2 < 2; c2++) {
        int o = c2 * 64 + oid;
        float bb = bd1[o];
        const float4* w4 = (const float4*)(Wd1 + o * 64 + q * 16);
        float4 w0 = w4[0], w1 = w4[1], w2 = w4[2], w3 = w4[3];
        const int kb = q * 16;
        #pragma unroll
        for (int r = 0; r < NPB; r++) {
            const float* x = &s_y0[r][kb];
            float s = w0.x*x[0] + w0.y*x[1] + w0.z*x[2] + w0.w*x[3]
                    + w1.x*x[4] + w1.y*x[5] + w1.z*x[6] + w1.w*x[7]
                    + w2.x*x[8] + w2.y*x[9] + w2.z*x[10] + w2.w*x[11]
                    + w3.x*x[12] + w3.y*x[13] + w3.z*x[14] + w3.w*x[15];
            s = red4(s);
            if (q == 0) s_y1[r][o] = leaky(bb + s);
        }
    }
    __syncthreads();
    // stage 3: 8 rows x 4 outputs, 8 threads per dot, + sigmoid
    {
        int r = tid >> 5, sub = tid & 31, o = sub >> 3, q8 = sub & 7;
        float p = dot16(Wd2 + o * 128 + q8 * 16, &s_y1[r][q8 * 16]);
        p = red8(p);
        int j = row0 + r;
        if (q8 == 0 && j < N_AMB)
            out[j * 4 + o] = 1.f / (1.f + __expf(-(bd2[o] + p)));
    }

    // ---- flag2 reset once ALL blocks have passed it ----
    if (tid == 0) {
        if (atomicAdd(&d_cnt2, 1) == NBLK - 1) {
            d_cnt2 = 0;
            __threadfence();
            *(volatile int*)&d_flag2 = 0;
        }
    }
}

// ---------------------------------------------------------------------------
extern "C" void kernel_launch(void* const* d_in, const int* in_sizes, int n_in,
                              void* d_out, int out_size) {
    const float* hidden = (const float*)d_in[0];
    const float* amb    = (const float*)d_in[1];
    const float* ta     = (const float*)d_in[2];
    const float* Wself  = (const float*)d_in[3];
    const float* bself  = (const float*)d_in[4];
    const float* Wmerge = (const float*)d_in[5];
    const float* bmerge = (const float*)d_in[6];
    const float* Wtrans = (const float*)d_in[7];
    const float* btrans = (const float*)d_in[8];
    const float* Wl     = (const float*)d_in[9];
    const float* Wr     = (const float*)d_in[10];
    const float* wattn  = (const float*)d_in[11];
    const float* Wd0    = (const float*)d_in[12];
    const float* bd0    = (const float*)d_in[13];
    const float* Wd1    = (const float*)d_in[14];
    const float* bd1    = (const float*)d_in[15];
    const float* Wd2    = (const float*)d_in[16];
    const float* bd2    = (const float*)d_in[17];
    float* out = (float*)d_out;

    mega<<<NBLK, 256>>>(hidden, amb, ta, Wself, bself, Wmerge, bmerge,
                        Wtrans, btrans, Wl, Wr, wattn,
                        Wd0, bd0, Wd1, bd1, Wd2, bd2, out);
}

// round 5
// speedup vs baseline: 1.4809x; 1.0525x over previous
#include <cuda_runtime.h>
#include <math.h>

#define RT 4
#define N_AMB 1023
#define SLOPE 0.2f
#define NPB 8
#define NBLK 128
#define NT 512

// ---- scratch (__device__ globals; no allocation allowed) ----
__device__ float d_gr0[256];
__device__ float d_pm[NBLK * 4];
__device__ float d_pz[NBLK * 4];
__device__ float d_pacc[NBLK * 256];
__device__ int   d_flag1;   // set by block 0 after routing; reset by cnt2-last
__device__ int   d_cnt1;    // partial-arrival counter; reset by cnt2-last
__device__ int   d_cnt2;    // exit counter; reset by its own last arriver

__device__ __forceinline__ float leaky(float x) { return x >= 0.f ? x : SLOPE * x; }
__device__ __forceinline__ float red8(float v) {
    v += __shfl_xor_sync(0xffffffffu, v, 1);
    v += __shfl_xor_sync(0xffffffffu, v, 2);
    v += __shfl_xor_sync(0xffffffffu, v, 4);
    return v;
}
__device__ __forceinline__ float warpsum(float v) {
    #pragma unroll
    for (int off = 16; off; off >>= 1) v += __shfl_xor_sync(0xffffffffu, v, off);
    return v;
}
__device__ __forceinline__ float dot8(const float* __restrict__ w, const float* __restrict__ x) {
    const float4* w4 = (const float4*)w;
    float4 a = w4[0], b = w4[1];
    return a.x*x[0] + a.y*x[1] + a.z*x[2] + a.w*x[3]
         + b.x*x[4] + b.y*x[5] + b.z*x[6] + b.w*x[7];
}
__device__ __forceinline__ float dot16(const float* __restrict__ w, const float* __restrict__ x) {
    const float4* w4 = (const float4*)w;
    float4 a = w4[0], b = w4[1], c = w4[2], d = w4[3];
    return a.x*x[0] + a.y*x[1] + a.z*x[2] + a.w*x[3]
         + b.x*x[4] + b.y*x[5] + b.z*x[6] + b.w*x[7]
         + c.x*x[8] + c.y*x[9] + c.z*x[10] + c.w*x[11]
         + d.x*x[12] + d.y*x[13] + d.z*x[14] + d.w*x[15];
}

__global__ void __launch_bounds__(NT, 1)
mega(const float* __restrict__ hidden, const float* __restrict__ amb,
     const float* __restrict__ ta,
     const float* __restrict__ Wself,  const float* __restrict__ bself,
     const float* __restrict__ Wmerge, const float* __restrict__ bmerge,
     const float* __restrict__ Wtrans, const float* __restrict__ btrans,
     const float* __restrict__ Wl,     const float* __restrict__ Wr,
     const float* __restrict__ wattn,
     const float* __restrict__ Wd0,    const float* __restrict__ bd0,
     const float* __restrict__ Wd1,    const float* __restrict__ bd1,
     const float* __restrict__ Wd2,    const float* __restrict__ bd2,
     float* __restrict__ out) {
    // 32 KB pool, aliased across phases:
    //  phase R (block0 routing): Wmerge cache [0..8192)
    //  phase A/B: s_al [0..2048), s_ar [2048..4096)
    //  phase C (combine): s_pm[0..512) s_pz[512..1024) s_scale[1024..1536) s_part[1536..2048)
    //  phase M (MLP): s_y0 [2048..2560), s_y1 [2560..3584)
    __shared__ float pool[8192];
    __shared__ float s_h[NPB][64];
    __shared__ float s_eall[4][8];
    __shared__ float s_wv[4][8];
    __shared__ float s_inh[64], s_avg[256], s_tmp[256], s_cat[128], s_new[64];
    __shared__ float s_M[4], s_Zi[4], s_h2[64], s_c0[64];

    float* const s_al    = pool;
    float* const s_ar    = pool + 2048;
    float* const s_pm    = pool;
    float* const s_pz    = pool + 512;
    float* const s_scale = pool + 1024;
    float* const s_part  = pool + 1536;
    float* const s_y0    = pool + 2048;
    float* const s_y1    = pool + 2560;

    const int tid = threadIdx.x, lane = tid & 31, warp = tid >> 5;
    const int oid = tid >> 3, q8 = tid & 7;      // 8 threads per output column
    const int blk = blockIdx.x;
    const int base = blk * NPB;

    // ---- node features for attention (512 values = 1 per thread) ----
    {
        int r = tid >> 6, k = tid & 63, j = base + r;
        if (j > 0) s_h[r][k] = amb[(j - 1) * 64 + k];   // j==0 filled by routing
    }

    // ================= block 0: routing chain =================
    if (blk == 0) {
        if (tid >= 256) {                 // prefetch Wmerge (32 KB) into pool
            int t = tid - 256;
            float4* dst = (float4*)pool;
            const float4* src = (const float4*)Wmerge;
            #pragma unroll
            for (int i = 0; i < 8; i++) dst[t + i * 256] = src[t + i * 256];
        } else {
            if (tid < 64) s_inh[tid] = hidden[tid];
            int rt = tid >> 6, oo = tid & 63;
            s_avg[tid] = (ta[(rt * 3 + 0) * 64 + oo] + ta[(rt * 3 + 1) * 64 + oo] +
                          ta[(rt * 3 + 2) * 64 + oo]) * (1.f / 3.f);
        }
        __syncthreads();
        if (tid < 256) {
            // hidden_1_0 = hidden @ Wself^T + bself (4 thr/out)
            int o4 = tid >> 2, q4 = tid & 3;
            float s = dot16(Wself + o4 * 64 + q4 * 16, &s_inh[q4 * 16]);
            s += __shfl_xor_sync(0xffffffffu, s, 1);
            s += __shfl_xor_sync(0xffffffffu, s, 2);
            if (q4 == 0) s_cat[o4] = bself[o4] + s;
            // tmp[rt] for all rt in parallel (1 thr/out)
            int rt = tid >> 6, oo = tid & 63;
            const float* av = &s_avg[rt * 64];
            float t = btrans[rt * 64 + oo];
            t += dot16(Wtrans + rt * 4096 + oo * 64,      av);
            t += dot16(Wtrans + rt * 4096 + oo * 64 + 16, av + 16);
            t += dot16(Wtrans + rt * 4096 + oo * 64 + 32, av + 32);
            t += dot16(Wtrans + rt * 4096 + oo * 64 + 48, av + 48);
            s_tmp[tid] = t;
        }
        __syncthreads();
        {   // serial merge chain, weights from smem (8 thr/out)
            float bm = bmerge[oid];
            for (int rt = 0; rt < RT; rt++) {
                if (tid < 64) s_cat[64 + tid] = s_tmp[rt * 64 + tid];
                __syncthreads();
                float m = dot16(&pool[oid * 128 + q8 * 16], &s_cat[q8 * 16]);
                m = red8(m);
                if (q8 == 0) s_new[oid] = leaky(bm + m);
                __syncthreads();
                if (tid < 64) s_cat[tid] = s_new[tid];
                __syncthreads();
            }
        }
        if (tid < 64) s_h[0][tid] = s_cat[tid];
        {   // g_r0 = hidden_1 @ Wr^T (2 thr/out)
            int o = tid >> 1, q2 = tid & 1;
            float g = dot16(Wr + o * 64 + q2 * 32,      &s_cat[q2 * 32])
                    + dot16(Wr + o * 64 + q2 * 32 + 16, &s_cat[q2 * 32 + 16]);
            g += __shfl_xor_sync(0xffffffffu, g, 1);
            if (q2 == 0) d_gr0[o] = g;
        }
        __threadfence();
        __syncthreads();
        if (tid == 0) *(volatile int*)&d_flag1 = 1;
    }
    __syncthreads();

    // ================= pass A: projections -> smem ===========================
    {
        const int kb = q8 * 8;
        #pragma unroll
        for (int c = 0; c < 4; c++) {
            int o = c * 64 + oid;
            const float4* wl4 = (const float4*)(Wl + o * 64 + kb);
            const float4* wr4 = (const float4*)(Wr + o * 64 + kb);
            float4 l0 = wl4[0], l1 = wl4[1], r0 = wr4[0], r1 = wr4[1];
            #pragma unroll
            for (int r = 0; r < NPB; r++) {
                const float* h = &s_h[r][kb];
                float xl = l0.x*h[0] + l0.y*h[1] + l0.z*h[2] + l0.w*h[3]
                         + l1.x*h[4] + l1.y*h[5] + l1.z*h[6] + l1.w*h[7];
                float xr = r0.x*h[0] + r0.y*h[1] + r0.z*h[2] + r0.w*h[3]
                         + r1.x*h[4] + r1.y*h[5] + r1.z*h[6] + r1.w*h[7];
                xl = red8(xl);
                xr = red8(xr);
                if (q8 == 0) {
                    s_al[(c * 8 + r) * 64 + oid] = xl;
                    s_ar[(c * 8 + r) * 64 + oid] = xr;
                }
            }
        }
    }
    if (blk != 0 && tid == 0) {
        volatile int* f = &d_flag1;
        while (!*f) __nanosleep(32);
        __threadfence();
    }
    __syncthreads();

    // ================= pass B: logits + online-softmax partial ===============
    #pragma unroll
    for (int it = 0; it < 2; it++) {         // 32 (c,r) tasks over 16 warps
        int task = warp * 2 + it;
        int c = task >> 3, r = task & 7;
        const float* alp = &s_al[(c * 8 + r) * 64];
        float v = leaky(alp[lane]      + d_gr0[c * 64 + lane])      * wattn[lane]
                + leaky(alp[lane + 32] + d_gr0[c * 64 + lane + 32]) * wattn[lane + 32];
        v = warpsum(v);
        if (lane == 0) s_eall[c][r] = v;
    }
    __syncthreads();
    if (tid < 4) {                           // per-head block stats
        int c = tid;
        float m = -1e30f;
        #pragma unroll
        for (int r = 0; r < NPB; r++) m = fmaxf(m, s_eall[c][r]);
        float z = 0.f;
        #pragma unroll
        for (int r = 0; r < NPB; r++) { float w = __expf(s_eall[c][r] - m); s_wv[c][r] = w; z += w; }
        d_pm[blk * 4 + c] = m;
        d_pz[blk * 4 + c] = z;
    }
    __syncthreads();
    if (tid < 256) {
        int c = tid >> 6;
        float acc = 0.f;
        #pragma unroll
        for (int r = 0; r < NPB; r++)
            acc = fmaf(s_wv[c][r], s_ar[(c * 8 + r) * 64 + (tid & 63)], acc);
        d_pacc[blk * 256 + tid] = acc;
    }
    // reload s_h with this block's MLP rows (overlaps the global sync below)
    {
        int r = tid >> 6, k = tid & 63, j = base + r;
        s_h[r][k] = (j < N_AMB) ? amb[j * 64 + k] : 0.f;
    }
    __threadfence();
    __syncthreads();
    if (tid == 0) {
        atomicAdd(&d_cnt1, 1);
        volatile int* c = &d_cnt1;
        while (*c < NBLK) __nanosleep(32);
        __threadfence();
    }
    __syncthreads();

    // ================= combine (redundant per block, fixed order) ============
    s_pm[tid] = d_pm[tid];
    s_pz[tid] = d_pz[tid];
    __syncthreads();
    if (warp < 4) {
        float mm = -1e30f;
        #pragma unroll
        for (int b = lane; b < NBLK; b += 32) mm = fmaxf(mm, s_pm[b * 4 + warp]);
        #pragma unroll
        for (int off = 16; off; off >>= 1) mm = fmaxf(mm, __shfl_xor_sync(0xffffffffu, mm, off));
        if (lane == 0) s_M[warp] = mm;
    }
    __syncthreads();
    s_scale[tid] = __expf(s_pm[tid] - s_M[tid & 3]);
    __syncthreads();
    if (warp < 4) {
        float zz = 0.f;
        #pragma unroll
        for (int b = lane; b < NBLK; b += 32) zz += s_pz[b * 4 + warp] * s_scale[b * 4 + warp];
        #pragma unroll
        for (int off = 16; off; off >>= 1) zz += __shfl_xor_sync(0xffffffffu, zz, off);
        if (lane == 0) s_Zi[warp] = 1.f / zz;
    }
    __syncthreads();
    {   // attn partial sums: thread handles output o over half the blocks
        int o = tid & 255, bh = tid >> 8, hh = o >> 6;
        float a = 0.f;
        #pragma unroll 8
        for (int b = bh * 64; b < bh * 64 + 64; b++)
            a = fmaf(d_pacc[b * 256 + o], s_scale[b * 4 + hh], a);
        s_part[bh * 256 + o] = a;
    }
    __syncthreads();
    if (tid < 64) {
        float h2 = 0.f;
        #pragma unroll
        for (int hh = 0; hh < 4; hh++)
            h2 += (s_part[hh * 64 + tid] + s_part[256 + hh * 64 + tid]) * s_Zi[hh];
        s_h2[tid] = 0.25f * h2;
    }
    __syncthreads();
    {   // c0[o] = bd0[o] + h2 . Wd0[o, 64:128]
        float p = dot8(Wd0 + oid * 128 + 64 + q8 * 8, &s_h2[q8 * 8]);
        p = red8(p);
        if (q8 == 0) s_c0[oid] = bd0[oid] + p;
    }
    __syncthreads();

    // ================= MLP over this block's 8 rows ==========================
    {   // stage 1: 64 outputs (const half folded into c0)
        const int kb = q8 * 8;
        const float4* w4 = (const float4*)(Wd0 + oid * 128 + kb);
        float4 a = w4[0], b = w4[1];
        float c0v = s_c0[oid];
        #pragma unroll
        for (int r = 0; r < NPB; r++) {
            const float* x = &s_h[r][kb];
            float s = a.x*x[0] + a.y*x[1] + a.z*x[2] + a.w*x[3]
                    + b.x*x[4] + b.y*x[5] + b.z*x[6] + b.w*x[7];
            s = red8(s);
            if (q8 == 0) s_y0[r * 64 + oid] = leaky(c0v + s);
        }
    }
    __syncthreads();
    {   // stage 2: 128 outputs
        const int kb = q8 * 8;
        #pragma unroll
        for (int c2 = 0; c2 < 2; c2++) {
            int o = c2 * 64 + oid;
            const float4* w4 = (const float4*)(Wd1 + o * 64 + kb);
            float4 a = w4[0], b = w4[1];
            float bb = bd1[o];
            #pragma unroll
            for (int r = 0; r < NPB; r++) {
                const float* x = &s_y0[r * 64 + kb];
                float s = a.x*x[0] + a.y*x[1] + a.z*x[2] + a.w*x[3]
                        + b.x*x[4] + b.y*x[5] + b.z*x[6] + b.w*x[7];
                s = red8(s);
                if (q8 == 0) s_y1[r * 128 + o] = leaky(bb + s);
            }
        }
    }
    __syncthreads();
    {   // stage 3: 8 rows x 4 outputs, 16 thr/dot, + sigmoid
        int r = tid >> 6, sub = tid & 63, o = sub >> 4, q16 = sub & 15;
        float p = dot8(Wd2 + o * 128 + q16 * 8, &s_y1[r * 128 + q16 * 8]);
        p += __shfl_xor_sync(0xffffffffu, p, 1);
        p += __shfl_xor_sync(0xffffffffu, p, 2);
        p += __shfl_xor_sync(0xffffffffu, p, 4);
        p += __shfl_xor_sync(0xffffffffu, p, 8);
        int j = base + r;
        if (q16 == 0 && j < N_AMB)
            out[j * 4 + o] = 1.f / (1.f + __expf(-(bd2[o] + p)));
    }

    // ---- counter/flag reset once ALL blocks are past every sync point ----
    if (tid == 0) {
        if (atomicAdd(&d_cnt2, 1) == NBLK - 1) {
            d_cnt1 = 0;
            d_flag1 = 0;
            __threadfence();
            *(volatile int*)&d_cnt2 = 0;
        }
    }
}

// ---------------------------------------------------------------------------
extern "C" void kernel_launch(void* const* d_in, const int* in_sizes, int n_in,
                              void* d_out, int out_size) {
    const float* hidden = (const float*)d_in[0];
    const float* amb    = (const float*)d_in[1];
    const float* ta     = (const float*)d_in[2];
    const float* Wself  = (const float*)d_in[3];
    const float* bself  = (const float*)d_in[4];
    const float* Wmerge = (const float*)d_in[5];
    const float* bmerge = (const float*)d_in[6];
    const float* Wtrans = (const float*)d_in[7];
    const float* btrans = (const float*)d_in[8];
    const float* Wl     = (const float*)d_in[9];
    const float* Wr     = (const float*)d_in[10];
    const float* wattn  = (const float*)d_in[11];
    const float* Wd0    = (const float*)d_in[12];
    const float* bd0    = (const float*)d_in[13];
    const float* Wd1    = (const float*)d_in[14];
    const float* bd1    = (const float*)d_in[15];
    const float* Wd2    = (const float*)d_in[16];
    const float* bd2    = (const float*)d_in[17];
    float* out = (float*)d_out;

    mega<<<NBLK, NT>>>(hidden, amb, ta, Wself, bself, Wmerge, bmerge,
                       Wtrans, btrans, Wl, Wr, wattn,
                       Wd0, bd0, Wd1, bd1, Wd2, bd2, out);
}

// round 6
// speedup vs baseline: 1.4823x; 1.0010x over previous
#include <cuda_runtime.h>
#include <math.h>

#define RT 4
#define N_AMB 1023
#define SLOPE 0.2f
#define NPB 8
#define NBLK 128
#define NT 512

// ---- scratch (__device__ globals; no allocation allowed) ----
__device__ float d_gr0[256];
__device__ float d_pm[NBLK * 4];
__device__ float d_pz[NBLK * 4];
__device__ float d_pacc[NBLK * 256];
__device__ int   d_flag1;   // set by block 0 after routing; reset by cnt2-last
__device__ int   d_cnt1;    // partial-arrival counter; reset by cnt2-last
__device__ int   d_cnt2;    // exit counter; reset by its own last arriver

__device__ __forceinline__ float leaky(float x) { return x >= 0.f ? x : SLOPE * x; }
__device__ __forceinline__ float red8(float v) {
    v += __shfl_xor_sync(0xffffffffu, v, 1);
    v += __shfl_xor_sync(0xffffffffu, v, 2);
    v += __shfl_xor_sync(0xffffffffu, v, 4);
    return v;
}
__device__ __forceinline__ float warpsum(float v) {
    #pragma unroll
    for (int off = 16; off; off >>= 1) v += __shfl_xor_sync(0xffffffffu, v, off);
    return v;
}
__device__ __forceinline__ float dot8(const float* __restrict__ w, const float* __restrict__ x) {
    const float4* w4 = (const float4*)w;
    float4 a = w4[0], b = w4[1];
    return a.x*x[0] + a.y*x[1] + a.z*x[2] + a.w*x[3]
         + b.x*x[4] + b.y*x[5] + b.z*x[6] + b.w*x[7];
}
__device__ __forceinline__ float dot16(const float* __restrict__ w, const float* __restrict__ x) {
    const float4* w4 = (const float4*)w;
    float4 a = w4[0], b = w4[1], c = w4[2], d = w4[3];
    return a.x*x[0] + a.y*x[1] + a.z*x[2] + a.w*x[3]
         + b.x*x[4] + b.y*x[5] + b.z*x[6] + b.w*x[7]
         + c.x*x[8] + c.y*x[9] + c.z*x[10] + c.w*x[11]
         + d.x*x[12] + d.y*x[13] + d.z*x[14] + d.w*x[15];
}

__global__ void __launch_bounds__(NT, 1)
mega(const float* __restrict__ hidden, const float* __restrict__ amb,
     const float* __restrict__ ta,
     const float* __restrict__ Wself,  const float* __restrict__ bself,
     const float* __restrict__ Wmerge, const float* __restrict__ bmerge,
     const float* __restrict__ Wtrans, const float* __restrict__ btrans,
     const float* __restrict__ Wl,     const float* __restrict__ Wr,
     const float* __restrict__ wattn,
     const float* __restrict__ Wd0,    const float* __restrict__ bd0,
     const float* __restrict__ Wd1,    const float* __restrict__ bd1,
     const float* __restrict__ Wd2,    const float* __restrict__ bd2,
     float* __restrict__ out) {
    // 32 KB pool, aliased across phases:
    //  phase R (block0 routing): Wmerge cache [0..8192)
    //  phase A/B: s_al [0..2048), s_ar [2048..4096)
    //  phase C (combine): s_pm[0..512) s_pz[512..1024) s_scale[1024..1536) s_part[1536..2048)
    //  phase M (MLP): s_y0 [2048..2560), s_y1 [2560..3584)
    __shared__ float pool[8192];
    __shared__ float s_h[NPB][64];
    __shared__ float s_eall[4][8];
    __shared__ float s_wv[4][8];
    __shared__ float s_inh[64], s_avg[256], s_tmp[256], s_cat[128], s_new[64];
    __shared__ float s_M[4], s_Zi[4], s_h2[64], s_c0[64];

    float* const s_al    = pool;
    float* const s_ar    = pool + 2048;
    float* const s_pm    = pool;
    float* const s_pz    = pool + 512;
    float* const s_scale = pool + 1024;
    float* const s_part  = pool + 1536;
    float* const s_y0    = pool + 2048;
    float* const s_y1    = pool + 2560;

    const int tid = threadIdx.x, lane = tid & 31, warp = tid >> 5;
    const int oid = tid >> 3, q8 = tid & 7;      // 8 threads per output column
    const int blk = blockIdx.x;
    const int base = blk * NPB;

    // ---- node features for attention (512 values = 1 per thread) ----
    {
        int r = tid >> 6, k = tid & 63, j = base + r;
        if (j > 0) s_h[r][k] = amb[(j - 1) * 64 + k];   // j==0 filled by routing
    }

    // ================= block 0: routing chain =================
    if (blk == 0) {
        if (tid >= 256) {                 // prefetch Wmerge (32 KB) into pool
            int t = tid - 256;
            float4* dst = (float4*)pool;
            const float4* src = (const float4*)Wmerge;
            #pragma unroll
            for (int i = 0; i < 8; i++) dst[t + i * 256] = src[t + i * 256];
        } else {
            if (tid < 64) s_inh[tid] = hidden[tid];
            int rt = tid >> 6, oo = tid & 63;
            s_avg[tid] = (ta[(rt * 3 + 0) * 64 + oo] + ta[(rt * 3 + 1) * 64 + oo] +
                          ta[(rt * 3 + 2) * 64 + oo]) * (1.f / 3.f);
        }
        __syncthreads();
        if (tid < 256) {
            // hidden_1_0 = hidden @ Wself^T + bself (4 thr/out)
            int o4 = tid >> 2, q4 = tid & 3;
            float s = dot16(Wself + o4 * 64 + q4 * 16, &s_inh[q4 * 16]);
            s += __shfl_xor_sync(0xffffffffu, s, 1);
            s += __shfl_xor_sync(0xffffffffu, s, 2);
            if (q4 == 0) s_cat[o4] = bself[o4] + s;
            // tmp[rt] for all rt in parallel (1 thr/out)
            int rt = tid >> 6, oo = tid & 63;
            const float* av = &s_avg[rt * 64];
            float t = btrans[rt * 64 + oo];
            t += dot16(Wtrans + rt * 4096 + oo * 64,      av);
            t += dot16(Wtrans + rt * 4096 + oo * 64 + 16, av + 16);
            t += dot16(Wtrans + rt * 4096 + oo * 64 + 32, av + 32);
            t += dot16(Wtrans + rt * 4096 + oo * 64 + 48, av + 48);
            s_tmp[tid] = t;
        }
        __syncthreads();
        {   // serial merge chain, weights from smem (8 thr/out)
            float bm = bmerge[oid];
            for (int rt = 0; rt < RT; rt++) {
                if (tid < 64) s_cat[64 + tid] = s_tmp[rt * 64 + tid];
                __syncthreads();
                float m = dot16(&pool[oid * 128 + q8 * 16], &s_cat[q8 * 16]);
                m = red8(m);
                if (q8 == 0) s_new[oid] = leaky(bm + m);
                __syncthreads();
                if (tid < 64) s_cat[tid] = s_new[tid];
                __syncthreads();
            }
        }
        if (tid < 64) s_h[0][tid] = s_cat[tid];
        {   // g_r0 = hidden_1 @ Wr^T (2 thr/out)
            int o = tid >> 1, q2 = tid & 1;
            float g = dot16(Wr + o * 64 + q2 * 32,      &s_cat[q2 * 32])
                    + dot16(Wr + o * 64 + q2 * 32 + 16, &s_cat[q2 * 32 + 16]);
            g += __shfl_xor_sync(0xffffffffu, g, 1);
            if (q2 == 0) d_gr0[o] = g;
        }
        __threadfence();
        __syncthreads();
        if (tid == 0) *(volatile int*)&d_flag1 = 1;
    }
    __syncthreads();

    // ================= pass A: projections -> smem ===========================
    {
        const int kb = q8 * 8;
        #pragma unroll
        for (int c = 0; c < 4; c++) {
            int o = c * 64 + oid;
            const float4* wl4 = (const float4*)(Wl + o * 64 + kb);
            const float4* wr4 = (const float4*)(Wr + o * 64 + kb);
            float4 l0 = wl4[0], l1 = wl4[1], r0 = wr4[0], r1 = wr4[1];
            #pragma unroll
            for (int r = 0; r < NPB; r++) {
                const float* h = &s_h[r][kb];
                float xl = l0.x*h[0] + l0.y*h[1] + l0.z*h[2] + l0.w*h[3]
                         + l1.x*h[4] + l1.y*h[5] + l1.z*h[6] + l1.w*h[7];
                float xr = r0.x*h[0] + r0.y*h[1] + r0.z*h[2] + r0.w*h[3]
                         + r1.x*h[4] + r1.y*h[5] + r1.z*h[6] + r1.w*h[7];
                xl = red8(xl);
                xr = red8(xr);
                if (q8 == 0) {
                    s_al[(c * 8 + r) * 64 + oid] = xl;
                    s_ar[(c * 8 + r) * 64 + oid] = xr;
                }
            }
        }
    }
    if (blk != 0 && tid == 0) {
        volatile int* f = &d_flag1;
        while (!*f) __nanosleep(32);
        __threadfence();
    }
    __syncthreads();

    // ================= pass B: logits + online-softmax partial ===============
    #pragma unroll
    for (int it = 0; it < 2; it++) {         // 32 (c,r) tasks over 16 warps
        int task = warp * 2 + it;
        int c = task >> 3, r = task & 7;
        const float* alp = &s_al[(c * 8 + r) * 64];
        float v = leaky(alp[lane]      + d_gr0[c * 64 + lane])      * wattn[lane]
                + leaky(alp[lane + 32] + d_gr0[c * 64 + lane + 32]) * wattn[lane + 32];
        v = warpsum(v);
        if (lane == 0) s_eall[c][r] = v;
    }
    __syncthreads();
    if (tid < 4) {                           // per-head block stats
        int c = tid;
        float m = -1e30f;
        #pragma unroll
        for (int r = 0; r < NPB; r++) m = fmaxf(m, s_eall[c][r]);
        float z = 0.f;
        #pragma unroll
        for (int r = 0; r < NPB; r++) { float w = __expf(s_eall[c][r] - m); s_wv[c][r] = w; z += w; }
        d_pm[blk * 4 + c] = m;
        d_pz[blk * 4 + c] = z;
    }
    __syncthreads();
    if (tid < 256) {
        int c = tid >> 6;
        float acc = 0.f;
        #pragma unroll
        for (int r = 0; r < NPB; r++)
            acc = fmaf(s_wv[c][r], s_ar[(c * 8 + r) * 64 + (tid & 63)], acc);
        d_pacc[blk * 256 + tid] = acc;
    }
    // reload s_h with this block's MLP rows (overlaps the global sync below)
    {
        int r = tid >> 6, k = tid & 63, j = base + r;
        s_h[r][k] = (j < N_AMB) ? amb[j * 64 + k] : 0.f;
    }
    __threadfence();
    __syncthreads();
    if (tid == 0) {
        atomicAdd(&d_cnt1, 1);
        volatile int* c = &d_cnt1;
        while (*c < NBLK) __nanosleep(32);
        __threadfence();
    }
    __syncthreads();

    // ================= combine (redundant per block, fixed order) ============
    s_pm[tid] = d_pm[tid];
    s_pz[tid] = d_pz[tid];
    __syncthreads();
    if (warp < 4) {
        float mm = -1e30f;
        #pragma unroll
        for (int b = lane; b < NBLK; b += 32) mm = fmaxf(mm, s_pm[b * 4 + warp]);
        #pragma unroll
        for (int off = 16; off; off >>= 1) mm = fmaxf(mm, __shfl_xor_sync(0xffffffffu, mm, off));
        if (lane == 0) s_M[warp] = mm;
    }
    __syncthreads();
    s_scale[tid] = __expf(s_pm[tid] - s_M[tid & 3]);
    __syncthreads();
    if (warp < 4) {
        float zz = 0.f;
        #pragma unroll
        for (int b = lane; b < NBLK; b += 32) zz += s_pz[b * 4 + warp] * s_scale[b * 4 + warp];
        #pragma unroll
        for (int off = 16; off; off >>= 1) zz += __shfl_xor_sync(0xffffffffu, zz, off);
        if (lane == 0) s_Zi[warp] = 1.f / zz;
    }
    __syncthreads();
    {   // attn partial sums: thread handles output o over half the blocks
        int o = tid & 255, bh = tid >> 8, hh = o >> 6;
        float a = 0.f;
        #pragma unroll 8
        for (int b = bh * 64; b < bh * 64 + 64; b++)
            a = fmaf(d_pacc[b * 256 + o], s_scale[b * 4 + hh], a);
        s_part[bh * 256 + o] = a;
    }
    __syncthreads();
    if (tid < 64) {
        float h2 = 0.f;
        #pragma unroll
        for (int hh = 0; hh < 4; hh++)
            h2 += (s_part[hh * 64 + tid] + s_part[256 + hh * 64 + tid]) * s_Zi[hh];
        s_h2[tid] = 0.25f * h2;
    }
    __syncthreads();
    {   // c0[o] = bd0[o] + h2 . Wd0[o, 64:128]
        float p = dot8(Wd0 + oid * 128 + 64 + q8 * 8, &s_h2[q8 * 8]);
        p = red8(p);
        if (q8 == 0) s_c0[oid] = bd0[oid] + p;
    }
    __syncthreads();

    // ================= MLP over this block's 8 rows ==========================
    {   // stage 1: 64 outputs (const half folded into c0)
        const int kb = q8 * 8;
        const float4* w4 = (const float4*)(Wd0 + oid * 128 + kb);
        float4 a = w4[0], b = w4[1];
        float c0v = s_c0[oid];
        #pragma unroll
        for (int r = 0; r < NPB; r++) {
            const float* x = &s_h[r][kb];
            float s = a.x*x[0] + a.y*x[1] + a.z*x[2] + a.w*x[3]
                    + b.x*x[4] + b.y*x[5] + b.z*x[6] + b.w*x[7];
            s = red8(s);
            if (q8 == 0) s_y0[r * 64 + oid] = leaky(c0v + s);
        }
    }
    __syncthreads();
    {   // stage 2: 128 outputs
        const int kb = q8 * 8;
        #pragma unroll
        for (int c2 = 0; c2 < 2; c2++) {
            int o = c2 * 64 + oid;
            const float4* w4 = (const float4*)(Wd1 + o * 64 + kb);
            float4 a = w4[0], b = w4[1];
            float bb = bd1[o];
            #pragma unroll
            for (int r = 0; r < NPB; r++) {
                const float* x = &s_y0[r * 64 + kb];
                float s = a.x*x[0] + a.y*x[1] + a.z*x[2] + a.w*x[3]
                        + b.x*x[4] + b.y*x[5] + b.z*x[6] + b.w*x[7];
                s = red8(s);
                if (q8 == 0) s_y1[r * 128 + o] = leaky(bb + s);
            }
        }
    }
    __syncthreads();
    {   // stage 3: 8 rows x 4 outputs, 16 thr/dot, + sigmoid
        int r = tid >> 6, sub = tid & 63, o = sub >> 4, q16 = sub & 15;
        float p = dot8(Wd2 + o * 128 + q16 * 8, &s_y1[r * 128 + q16 * 8]);
        p += __shfl_xor_sync(0xffffffffu, p, 1);
        p += __shfl_xor_sync(0xffffffffu, p, 2);
        p += __shfl_xor_sync(0xffffffffu, p, 4);
        p += __shfl_xor_sync(0xffffffffu, p, 8);
        int j = base + r;
        if (q16 == 0 && j < N_AMB)
            out[j * 4 + o] = 1.f / (1.f + __expf(-(bd2[o] + p)));
    }

    // ---- counter/flag reset once ALL blocks are past every sync point ----
    if (tid == 0) {
        if (atomicAdd(&d_cnt2, 1) == NBLK - 1) {
            d_cnt1 = 0;
            d_flag1 = 0;
            __threadfence();
            *(volatile int*)&d_cnt2 = 0;
        }
    }
}

// ---------------------------------------------------------------------------
extern "C" void kernel_launch(void* const* d_in, const int* in_sizes, int n_in,
                              void* d_out, int out_size) {
    const float* hidden = (const float*)d_in[0];
    const float* amb    = (const float*)d_in[1];
    const float* ta     = (const float*)d_in[2];
    const float* Wself  = (const float*)d_in[3];
    const float* bself  = (const float*)d_in[4];
    const float* Wmerge = (const float*)d_in[5];
    const float* bmerge = (const float*)d_in[6];
    const float* Wtrans = (const float*)d_in[7];
    const float* btrans = (const float*)d_in[8];
    const float* Wl     = (const float*)d_in[9];
    const float* Wr     = (const float*)d_in[10];
    const float* wattn  = (const float*)d_in[11];
    const float* Wd0    = (const float*)d_in[12];
    const float* bd0    = (const float*)d_in[13];
    const float* Wd1    = (const float*)d_in[14];
    const float* bd1    = (const float*)d_in[15];
    const float* Wd2    = (const float*)d_in[16];
    const float* bd2    = (const float*)d_in[17];
    float* out = (float*)d_out;

    mega<<<NBLK, NT>>>(hidden, amb, ta, Wself, bself, Wmerge, bmerge,
                       Wtrans, btrans, Wl, Wr, wattn,
                       Wd0, bd0, Wd1, bd1, Wd2, bd2, out);
}

// round 9
// speedup vs baseline: 1.5902x; 1.0727x over previous
#include <cuda_runtime.h>
#include <math.h>

#define RT 4
#define N_AMB 1023
#define SLOPE 0.2f
#define NPB 8
#define NODE_BLKS 128
#define GRID 129
#define NT 512

__device__ float d_gr0[256];
__device__ float d_pm[GRID * 4];
__device__ float d_pz[GRID * 4];
__device__ float d_pacc[GRID * 256];
__device__ int   d_flag1, d_go, d_cnt1, d_cnt2;

__device__ __forceinline__ float leaky(float x) { return x >= 0.f ? x : SLOPE * x; }
__device__ __forceinline__ float red8(float v) {
    v += __shfl_xor_sync(0xffffffffu, v, 1);
    v += __shfl_xor_sync(0xffffffffu, v, 2);
    v += __shfl_xor_sync(0xffffffffu, v, 4);
    return v;
}
__device__ __forceinline__ float warpsum(float v) {
    #pragma unroll
    for (int off = 16; off; off >>= 1) v += __shfl_xor_sync(0xffffffffu, v, off);
    return v;
}
__device__ __forceinline__ float dot8(const float* __restrict__ w, const float* __restrict__ x) {
    const float4* w4 = (const float4*)w;
    float4 a = w4[0], b = w4[1];
    return a.x*x[0] + a.y*x[1] + a.z*x[2] + a.w*x[3]
         + b.x*x[4] + b.y*x[5] + b.z*x[6] + b.w*x[7];
}
__device__ __forceinline__ float dot16(const float* __restrict__ w, const float* __restrict__ x) {
    const float4* w4 = (const float4*)w;
    float4 a = w4[0], b = w4[1], c = w4[2], d = w4[3];
    return a.x*x[0] + a.y*x[1] + a.z*x[2] + a.w*x[3]
         + b.x*x[4] + b.y*x[5] + b.z*x[6] + b.w*x[7]
         + c.x*x[8] + c.y*x[9] + c.z*x[10] + c.w*x[11]
         + d.x*x[12] + d.y*x[13] + d.z*x[14] + d.w*x[15];
}

__global__ void __launch_bounds__(NT, 1)
mega(const float* __restrict__ hidden, const float* __restrict__ amb,
     const float* __restrict__ ta,
     const float* __restrict__ Wself,  const float* __restrict__ bself,
     const float* __restrict__ Wmerge, const float* __restrict__ bmerge,
     const float* __restrict__ Wtrans, const float* __restrict__ btrans,
     const float* __restrict__ Wl,     const float* __restrict__ Wr,
     const float* __restrict__ wattn,
     const float* __restrict__ Wd0,    const float* __restrict__ bd0,
     const float* __restrict__ Wd1,    const float* __restrict__ bd1,
     const float* __restrict__ Wd2,    const float* __restrict__ bd2,
     float* __restrict__ out) {
    __shared__ float pool[8192];         // Wmerge cache / al,ar / combine / y0,y1
    __shared__ float s_h[NPB * 64];      // node==MLP rows; routing: gl|gr
    __shared__ float s_eall[4][8], s_wv[4][8];
    __shared__ float s_inh[64], s_avg[256], s_tmp[256], s_cat[128], s_new[64];
    __shared__ float s_M[4], s_Zi[4], s_h2[64], s_c0[64], s_e0[8];

    float* const s_al    = pool;
    float* const s_ar    = pool + 2048;
    float* const s_pm    = pool;
    float* const s_pz    = pool + 516;
    float* const s_scale = pool + 1032;
    float* const s_part  = pool + 1548;
    float* const s_y0    = pool + 2560;
    float* const s_y1    = pool + 3584;

    const int tid = threadIdx.x, lane = tid & 31, warp = tid >> 5;
    const int oid = tid >> 3, q8 = tid & 7;
    const int blk = blockIdx.x;
    const int base = blk * NPB;

    // ===================== block 128: routing + node 0 =====================
    if (blk == NODE_BLKS) {
        if (tid >= 256) {                 // prefetch Wmerge 32KB
            int t = tid - 256;
            float4* dst = (float4*)pool;
            const float4* src = (const float4*)Wmerge;
            #pragma unroll
            for (int i = 0; i < 8; i++) dst[t + i * 256] = src[t + i * 256];
        } else {
            if (tid < 64) s_inh[tid] = hidden[tid];
            int rt = tid >> 6, oo = tid & 63;
            s_avg[tid] = (ta[(rt * 3 + 0) * 64 + oo] + ta[(rt * 3 + 1) * 64 + oo] +
                          ta[(rt * 3 + 2) * 64 + oo]) * (1.f / 3.f);
        }
        __syncthreads();
        if (tid < 256) {
            int o4 = tid >> 2, q4 = tid & 3;
            float s = dot16(Wself + o4 * 64 + q4 * 16, &s_inh[q4 * 16]);
            s += __shfl_xor_sync(0xffffffffu, s, 1);
            s += __shfl_xor_sync(0xffffffffu, s, 2);
            if (q4 == 0) s_cat[o4] = bself[o4] + s;
            int rt = tid >> 6, oo = tid & 63;
            const float* av = &s_avg[rt * 64];
            float t = btrans[rt * 64 + oo];
            t += dot16(Wtrans + rt * 4096 + oo * 64,      av);
            t += dot16(Wtrans + rt * 4096 + oo * 64 + 16, av + 16);
            t += dot16(Wtrans + rt * 4096 + oo * 64 + 32, av + 32);
            t += dot16(Wtrans + rt * 4096 + oo * 64 + 48, av + 48);
            s_tmp[tid] = t;
        }
        __syncthreads();
        {   // serial merge chain from smem Wmerge
            float bm = bmerge[oid];
            for (int rt = 0; rt < RT; rt++) {
                if (tid < 64) s_cat[64 + tid] = s_tmp[rt * 64 + tid];
                __syncthreads();
                float m = dot16(&pool[oid * 128 + q8 * 16], &s_cat[q8 * 16]);
                m = red8(m);
                if (q8 == 0) s_new[oid] = leaky(bm + m);
                __syncthreads();
                if (tid < 64) s_cat[tid] = s_new[tid];
                __syncthreads();
            }
        }
        {   // gl0 -> s_h[0..255], gr0 -> s_h[256..511] + d_gr0
            int o = tid >> 1, q2 = tid & 1;
            float gl = dot16(Wl + o * 64 + q2 * 32,      &s_cat[q2 * 32])
                     + dot16(Wl + o * 64 + q2 * 32 + 16, &s_cat[q2 * 32 + 16]);
            float gr = dot16(Wr + o * 64 + q2 * 32,      &s_cat[q2 * 32])
                     + dot16(Wr + o * 64 + q2 * 32 + 16, &s_cat[q2 * 32 + 16]);
            gl += __shfl_xor_sync(0xffffffffu, gl, 1);
            gr += __shfl_xor_sync(0xffffffffu, gr, 1);
            if (q2 == 0) { s_h[o] = gl; s_h[256 + o] = gr; d_gr0[o] = gr; }
        }
        __threadfence();
        __syncthreads();
        if (tid == 0) *(volatile int*)&d_flag1 = 1;     // release g_r0
        if (warp < 8) {                   // e0[h]
            int h = warp >> 1, half = warp & 1, f = half * 32 + lane;
            float c = leaky(s_h[h * 64 + f] + s_h[256 + h * 64 + f]) * wattn[f];
            c = warpsum(c);
            if (lane == 0) s_e0[h * 2 + half] = c;
        }
        __syncthreads();
        if (tid < 4) { d_pm[NODE_BLKS * 4 + tid] = s_e0[tid * 2] + s_e0[tid * 2 + 1];
                       d_pz[NODE_BLKS * 4 + tid] = 1.f; }
        if (tid < 256) d_pacc[NODE_BLKS * 256 + tid] = s_h[256 + tid];
        __threadfence();
        __syncthreads();
        if (tid == 0) {
            if (atomicAdd(&d_cnt1, 1) == GRID - 1) { __threadfence(); *(volatile int*)&d_go = 1; }
            if (atomicAdd(&d_cnt2, 1) == GRID - 1) {
                d_cnt1 = 0; d_go = 0; d_flag1 = 0;
                __threadfence();
                *(volatile int*)&d_cnt2 = 0;
            }
        }
        return;
    }

    // ===================== node blocks 0..127 =====================
    {   // amb rows base..base+7 (clamped pad) serve attention AND MLP
        int r = tid >> 6, k = tid & 63;
        int ar = base + r; if (ar >= N_AMB) ar = N_AMB - 1;
        s_h[r * 64 + k] = amb[ar * 64 + k];
    }
    __syncthreads();

    // pass A: projections -> s_al/s_ar (q8 split)
    {
        const int kb = q8 * 8;
        #pragma unroll
        for (int c = 0; c < 4; c++) {
            int o = c * 64 + oid;
            const float4* wl4 = (const float4*)(Wl + o * 64 + kb);
            const float4* wr4 = (const float4*)(Wr + o * 64 + kb);
            float4 l0 = wl4[0], l1 = wl4[1], r0 = wr4[0], r1 = wr4[1];
            #pragma unroll
            for (int r = 0; r < NPB; r++) {
                const float* h = &s_h[r * 64 + kb];
                float xl = l0.x*h[0] + l0.y*h[1] + l0.z*h[2] + l0.w*h[3]
                         + l1.x*h[4] + l1.y*h[5] + l1.z*h[6] + l1.w*h[7];
                float xr = r0.x*h[0] + r0.y*h[1] + r0.z*h[2] + r0.w*h[3]
                         + r1.x*h[4] + r1.y*h[5] + r1.z*h[6] + r1.w*h[7];
                xl = red8(xl);
                xr = red8(xr);
                if (q8 == 0) {
                    s_al[(c * 8 + r) * 64 + oid] = xl;
                    s_ar[(c * 8 + r) * 64 + oid] = xr;
                }
            }
        }
    }
    // MLP stage-1 partial dots (independent of barrier; overlaps cold Wd0)
    float p1[NPB];
    {
        const int kb = q8 * 8;
        const float4* w4 = (const float4*)(Wd0 + oid * 128 + kb);
        float4 a = w4[0], b = w4[1];
        #pragma unroll
        for (int r = 0; r < NPB; r++) {
            const float* x = &s_h[r * 64 + kb];
            p1[r] = a.x*x[0] + a.y*x[1] + a.z*x[2] + a.w*x[3]
                  + b.x*x[4] + b.y*x[5] + b.z*x[6] + b.w*x[7];
        }
    }
    if (tid == 0) {
        volatile int* f = &d_flag1;
        while (!*f) __nanosleep(32);
        __threadfence();
    }
    __syncthreads();

    // pass B: logits + per-head stats + pacc
    #pragma unroll
    for (int it = 0; it < 2; it++) {
        int task = warp * 2 + it;
        int c = task >> 3, r = task & 7;
        const float* alp = &s_al[(c * 8 + r) * 64];
        float v = leaky(alp[lane]      + d_gr0[c * 64 + lane])      * wattn[lane]
                + leaky(alp[lane + 32] + d_gr0[c * 64 + lane + 32]) * wattn[lane + 32];
        v = warpsum(v);
        if (lane == 0) s_eall[c][r] = (base + r < N_AMB) ? v : -1e30f;
    }
    __syncthreads();
    if (tid < 4) {
        int c = tid;
        float m = -1e30f;
        #pragma unroll
        for (int r = 0; r < NPB; r++) m = fmaxf(m, s_eall[c][r]);
        float z = 0.f;
        #pragma unroll
        for (int r = 0; r < NPB; r++) { float w = __expf(s_eall[c][r] - m); s_wv[c][r] = w; z += w; }
        d_pm[blk * 4 + c] = m;
        d_pz[blk * 4 + c] = z;
    }
    __syncthreads();
    if (tid < 256) {
        int c = tid >> 6;
        float acc = 0.f;
        #pragma unroll
        for (int r = 0; r < NPB; r++)
            acc = fmaf(s_wv[c][r], s_ar[(c * 8 + r) * 64 + (tid & 63)], acc);
        d_pacc[blk * 256 + tid] = acc;
    }
    __threadfence();
    __syncthreads();
    if (tid == 0) {
        if (atomicAdd(&d_cnt1, 1) == GRID - 1) {
            __threadfence();
            *(volatile int*)&d_go = 1;
        } else {
            volatile int* g = &d_go;
            while (!*g) __nanosleep(32);
            __threadfence();
        }
    }
    __syncthreads();

    // combine (redundant per block, fixed order => deterministic)
    for (int i = tid; i < GRID * 4; i += NT) { s_pm[i] = d_pm[i]; s_pz[i] = d_pz[i]; }
    __syncthreads();
    if (warp < 4) {
        float mm = -1e30f;
        for (int b = lane; b < GRID; b += 32) mm = fmaxf(mm, s_pm[b * 4 + warp]);
        #pragma unroll
        for (int off = 16; off; off >>= 1) mm = fmaxf(mm, __shfl_xor_sync(0xffffffffu, mm, off));
        if (lane == 0) s_M[warp] = mm;
    }
    __syncthreads();
    for (int i = tid; i < GRID * 4; i += NT) s_scale[i] = __expf(s_pm[i] - s_M[i & 3]);
    __syncthreads();
    if (warp < 4) {
        float zz = 0.f;
        for (int b = lane; b < GRID; b += 32) zz += s_pz[b * 4 + warp] * s_scale[b * 4 + warp];
        #pragma unroll
        for (int off = 16; off; off >>= 1) zz += __shfl_xor_sync(0xffffffffu, zz, off);
        if (lane == 0) s_Zi[warp] = 1.f / zz;
    }
    __syncthreads();
    {
        int o = tid & 255, half = tid >> 8, hh = o >> 6;
        int b0 = half ? 65 : 0, b1 = half ? GRID : 65;
        float a = 0.f;
        #pragma unroll 16
        for (int b = b0; b < b1; b++)
            a = fmaf(d_pacc[b * 256 + o], s_scale[b * 4 + hh], a);
        s_part[half * 256 + o] = a;
    }
    __syncthreads();
    if (tid < 64) {
        float h2 = 0.f;
        #pragma unroll
        for (int hh = 0; hh < 4; hh++)
            h2 += (s_part[hh * 64 + tid] + s_part[256 + hh * 64 + tid]) * s_Zi[hh];
        s_h2[tid] = 0.25f * h2;
    }
    __syncthreads();
    {   // c0[o] = bd0[o] + h2 . Wd0[o,64:128]
        float p = dot8(Wd0 + oid * 128 + 64 + q8 * 8, &s_h2[q8 * 8]);
        p = red8(p);
        if (q8 == 0) s_c0[oid] = bd0[oid] + p;
    }
    __syncthreads();

    // MLP finish
    {   // stage 1: reduce hoisted partials
        float c0v = s_c0[oid];
        #pragma unroll
        for (int r = 0; r < NPB; r++) {
            float s = red8(p1[r]);
            if (q8 == 0) s_y0[r * 64 + oid] = leaky(c0v + s);
        }
    }
    __syncthreads();
    {   // stage 2: 128 outputs
        const int kb = q8 * 8;
        #pragma unroll
        for (int c2 = 0; c2 < 2; c2++) {
            int o = c2 * 64 + oid;
            const float4* w4 = (const float4*)(Wd1 + o * 64 + kb);
            float4 a = w4[0], b = w4[1];
            float bb = bd1[o];
            #pragma unroll
            for (int r = 0; r < NPB; r++) {
                const float* x = &s_y0[r * 64 + kb];
                float s = a.x*x[0] + a.y*x[1] + a.z*x[2] + a.w*x[3]
                        + b.x*x[4] + b.y*x[5] + b.z*x[6] + b.w*x[7];
                s = red8(s);
                if (q8 == 0) s_y1[r * 128 + o] = leaky(bb + s);
            }
        }
    }
    __syncthreads();
    {   // stage 3 + sigmoid
        int r = tid >> 6, sub = tid & 63, o = sub >> 4, q16 = sub & 15;
        float p = dot8(Wd2 + o * 128 + q16 * 8, &s_y1[r * 128 + q16 * 8]);
        p += __shfl_xor_sync(0xffffffffu, p, 1);
        p += __shfl_xor_sync(0xffffffffu, p, 2);
        p += __shfl_xor_sync(0xffffffffu, p, 4);
        p += __shfl_xor_sync(0xffffffffu, p, 8);
        int ar = base + r;
        if (q16 == 0 && ar < N_AMB)
            out[ar * 4 + o] = 1.f / (1.f + __expf(-(bd2[o] + p)));
    }

    if (tid == 0) {
        if (atomicAdd(&d_cnt2, 1) == GRID - 1) {
            d_cnt1 = 0; d_go = 0; d_flag1 = 0;
            __threadfence();
            *(volatile int*)&d_cnt2 = 0;
        }
    }
}

extern "C" void kernel_launch(void* const* d_in, const int* in_sizes, int n_in,
                              void* d_out, int out_size) {
    const float* hidden = (const float*)d_in[0];
    const float* amb    = (const float*)d_in[1];
    const float* ta     = (const float*)d_in[2];
    const float* Wself  = (const float*)d_in[3];
    const float* bself  = (const float*)d_in[4];
    const float* Wmerge = (const float*)d_in[5];
    const float* bmerge = (const float*)d_in[6];
    const float* Wtrans = (const float*)d_in[7];
    const float* btrans = (const float*)d_in[8];
    const float* Wl     = (const float*)d_in[9];
    const float* Wr     = (const float*)d_in[10];
    const float* wattn  = (const float*)d_in[11];
    const float* Wd0    = (const float*)d_in[12];
    const float* bd0    = (const float*)d_in[13];
    const float* Wd1    = (const float*)d_in[14];
    const float* bd1    = (const float*)d_in[15];
    const float* Wd2    = (const float*)d_in[16];
    const float* bd2    = (const float*)d_in[17];
    float* out = (float*)d_out;

    mega<<<GRID, NT>>>(hidden, amb, ta, Wself, bself, Wmerge, bmerge,
                       Wtrans, btrans, Wl, Wr, wattn,
                       Wd0, bd0, Wd1, bd1, Wd2, bd2, out);
}